// round 1
// baseline (speedup 1.0000x reference)
#include <cuda_runtime.h>

#define NUM_PL 50000
#define NUM_TR 100000
#define NUM_AR 10000
#define NTOT   160000
#define HID    64
#define FEAT   128
#define OFF_TR NUM_PL
#define OFF_AR (NUM_PL + NUM_TR)

// Scratch (device globals — no allocation allowed)
__device__ float g_X[(size_t)NTOT * HID];    // node features, updated in place
__device__ float g_AGG[(size_t)NTOT * HID];  // neighbor-sum accumulator
__device__ int   g_DEG[NTOT];                // degree counts

// ---------------------------------------------------------------------------
__global__ void zero_kernel(int n4, int nd) {
    int i = blockIdx.x * blockDim.x + threadIdx.x;
    int stride = gridDim.x * blockDim.x;
    float4* a4 = reinterpret_cast<float4*>(g_AGG);
    const float4 z = make_float4(0.f, 0.f, 0.f, 0.f);
    for (int k = i; k < n4; k += stride) a4[k] = z;
    for (int k = i; k < nd; k += stride) g_DEG[k] = 0;
}

// x[node] = emb[node] + type_row  (playlists / artists)
__global__ void init_emb_kernel(const float* __restrict__ emb,
                                const float* __restrict__ te_row,
                                int nodeOff, int n) {
    int i = blockIdx.x * blockDim.x + threadIdx.x;
    if (i < n) g_X[(size_t)nodeOff * HID + i] = emb[i] + te_row[i & (HID - 1)];
}

// tracks: x = track_x @ W^T + b + type_emb[1]
// block = 256 threads, 16 tracks per block. W kept transposed in shared.
__global__ void track_linear_kernel(const float* __restrict__ tx,
                                    const float* __restrict__ W,
                                    const float* __restrict__ b,
                                    const float* __restrict__ te) {
    __shared__ float shW[FEAT * HID];   // [k][j]  32KB
    __shared__ float shR[16 * FEAT];    // 8KB
    int tid = threadIdx.x;
    for (int i = tid; i < FEAT * HID; i += 256) {
        int j = i >> 7, k = i & (FEAT - 1);   // W[j][k]
        shW[k * HID + j] = W[i];
    }
    int j = tid & 63, g = tid >> 6;           // g in 0..3, 4 tracks each
    float bias = b[j] + te[HID + j];          // type_emb row 1
    int base = blockIdx.x * 16;
    for (int i = tid; i < 16 * FEAT; i += 256)
        shR[i] = tx[(size_t)base * FEAT + i];
    __syncthreads();
    float acc[4] = {bias, bias, bias, bias};
#pragma unroll
    for (int k = 0; k < FEAT; k++) {
        float w = shW[k * HID + j];
#pragma unroll
        for (int t = 0; t < 4; t++) acc[t] += shR[(g * 4 + t) * FEAT + k] * w;
    }
#pragma unroll
    for (int t = 0; t < 4; t++)
        g_X[(size_t)(OFF_TR + base + g * 4 + t) * HID + j] = acc[t];
}

// Each pair contributes degree to both endpoints.
__global__ void deg_kernel(const int* __restrict__ A, const int* __restrict__ B,
                           int n, int offA, int offB) {
    int i = blockIdx.x * blockDim.x + threadIdx.x;
    if (i < n) {
        atomicAdd(&g_DEG[A[i] + offA], 1);
        atomicAdd(&g_DEG[B[i] + offB], 1);
    }
}

// One warp per undirected pair. Lanes 0-15: x[a]->agg[b] (float4 q=lane),
// lanes 16-31: x[b]->agg[a]. Vector reduction, no return value.
__global__ void scatter_kernel(const int* __restrict__ A, const int* __restrict__ B,
                               int n, int offA, int offB) {
    int w = (blockIdx.x * blockDim.x + threadIdx.x) >> 5;
    if (w >= n) return;
    int lane = threadIdx.x & 31;
    int a = A[w] + offA;
    int b = B[w] + offB;
    int srcRow, dstRow, q;
    if (lane < 16) { srcRow = a; dstRow = b; q = lane; }
    else           { srcRow = b; dstRow = a; q = lane - 16; }
    float4 v = reinterpret_cast<const float4*>(g_X)[(size_t)srcRow * 16 + q];
    float4* p = reinterpret_cast<float4*>(g_AGG) + (size_t)dstRow * 16 + q;
    asm volatile("red.global.add.v4.f32 [%0], {%1,%2,%3,%4};"
                 :: "l"(p), "f"(v.x), "f"(v.y), "f"(v.z), "f"(v.w)
                 : "memory");
}

// x_new = relu((agg/deg) @ Wl^T + bl + x @ Wr^T). In-place safe:
// per-node rows read into shared before any write; blocks own disjoint nodes.
// OUT == nullptr -> write g_X (layer 0); otherwise write OUT (final layer).
__global__ void update_kernel(const float* __restrict__ Wl,
                              const float* __restrict__ bl,
                              const float* __restrict__ Wr,
                              float* __restrict__ OUT) {
    __shared__ float shWl[HID * HID];   // [k][j]
    __shared__ float shWr[HID * HID];
    __shared__ float shA[16 * HID];
    __shared__ float shX[16 * HID];
    int tid = threadIdx.x;
    for (int i = tid; i < HID * HID; i += 256) {
        int j = i >> 6, k = i & 63;     // W[j][k]
        shWl[k * HID + j] = Wl[i];
        shWr[k * HID + j] = Wr[i];
    }
    int j = tid & 63, g = tid >> 6;
    float bias = bl[j];
    int base = blockIdx.x * 16;
    for (int i = tid; i < 16 * HID; i += 256) {
        int node = base + (i >> 6);
        int d = g_DEG[node]; if (d < 1) d = 1;
        shA[i] = g_AGG[(size_t)node * HID + (i & 63)] * (1.0f / (float)d);
        shX[i] = g_X[(size_t)node * HID + (i & 63)];
    }
    __syncthreads();
    float acc[4] = {bias, bias, bias, bias};
#pragma unroll
    for (int k = 0; k < HID; k++) {
        float wl = shWl[k * HID + j];
        float wr = shWr[k * HID + j];
#pragma unroll
        for (int t = 0; t < 4; t++) {
            int nn = g * 4 + t;
            acc[t] += shA[nn * HID + k] * wl + shX[nn * HID + k] * wr;
        }
    }
    float* o = OUT ? OUT : g_X;
#pragma unroll
    for (int t = 0; t < 4; t++)
        o[(size_t)(base + g * 4 + t) * HID + j] = fmaxf(acc[t], 0.f);
}

// ---------------------------------------------------------------------------
extern "C" void kernel_launch(void* const* d_in, const int* in_sizes, int n_in,
                              void* d_out, int out_size) {
    const float* track_x      = (const float*)d_in[0];
    const int*   pl_tr_src    = (const int*)d_in[1];
    const int*   pl_tr_dst    = (const int*)d_in[2];
    const int*   tr_ar_src    = (const int*)d_in[3];
    const int*   tr_ar_dst    = (const int*)d_in[4];
    const float* playlist_emb = (const float*)d_in[5];
    const float* artist_emb   = (const float*)d_in[6];
    const float* track_W      = (const float*)d_in[7];
    const float* track_b      = (const float*)d_in[8];
    const float* type_emb     = (const float*)d_in[9];
    const float* conv_Wl      = (const float*)d_in[10];
    const float* conv_bl      = (const float*)d_in[11];
    const float* conv_Wr      = (const float*)d_in[12];
    float* out = (float*)d_out;

    int nE1 = in_sizes[1];   // pl<->tr pairs (2,000,000)
    int nE2 = in_sizes[3];   // tr<->ar pairs (100,000)
    const int AGG4 = NTOT * HID / 4;

    // init
    zero_kernel<<<2048, 256>>>(AGG4, NTOT);
    init_emb_kernel<<<(NUM_PL * HID + 255) / 256, 256>>>(playlist_emb, type_emb, 0, NUM_PL * HID);
    init_emb_kernel<<<(NUM_AR * HID + 255) / 256, 256>>>(artist_emb, type_emb + 2 * HID, OFF_AR, NUM_AR * HID);
    track_linear_kernel<<<NUM_TR / 16, 256>>>(track_x, track_W, track_b, type_emb);
    deg_kernel<<<(nE1 + 255) / 256, 256>>>(pl_tr_src, pl_tr_dst, nE1, 0, OFF_TR);
    deg_kernel<<<(nE2 + 255) / 256, 256>>>(tr_ar_src, tr_ar_dst, nE2, OFF_TR, OFF_AR);

    // layer 0
    scatter_kernel<<<(nE1 + 7) / 8, 256>>>(pl_tr_src, pl_tr_dst, nE1, 0, OFF_TR);
    scatter_kernel<<<(nE2 + 7) / 8, 256>>>(tr_ar_src, tr_ar_dst, nE2, OFF_TR, OFF_AR);
    update_kernel<<<NTOT / 16, 256>>>(conv_Wl, conv_bl, conv_Wr, nullptr);

    // layer 1
    zero_kernel<<<2048, 256>>>(AGG4, 0);
    scatter_kernel<<<(nE1 + 7) / 8, 256>>>(pl_tr_src, pl_tr_dst, nE1, 0, OFF_TR);
    scatter_kernel<<<(nE2 + 7) / 8, 256>>>(tr_ar_src, tr_ar_dst, nE2, OFF_TR, OFF_AR);
    update_kernel<<<NTOT / 16, 256>>>(conv_Wl + HID * HID, conv_bl + HID, conv_Wr + HID * HID, out);
}

// round 3
// speedup vs baseline: 1.9629x; 1.9629x over previous
#include <cuda_runtime.h>

#define NUM_PL 50000
#define NUM_TR 100000
#define NUM_AR 10000
#define NTOT   160000
#define HID    64
#define FEAT   128
#define OFF_TR NUM_PL
#define OFF_AR (NUM_PL + NUM_TR)
#define NEDGE  4200000   // total directed incidences (2*(2,000,000+100,000))

// Scratch (device globals — no allocation allowed)
__device__ float g_X[(size_t)NTOT * HID];    // node features (updated in place)
__device__ float g_AGG[(size_t)NTOT * HID];  // per-layer neighbor means
__device__ int   g_DEG[NTOT];
__device__ int   g_CUR[NTOT];
__device__ int   g_ROWPTR[NTOT + 1];
__device__ int   g_ADJ[NEDGE];

// ---------------------------------------------------------------------------
__global__ void zero_kernel() {
    int i = blockIdx.x * blockDim.x + threadIdx.x;
    int stride = gridDim.x * blockDim.x;
    for (int k = i; k < NTOT; k += stride) { g_DEG[k] = 0; g_CUR[k] = 0; }
}

// x[node] = emb[node] + type_row  (playlists / artists)
__global__ void init_emb_kernel(const float* __restrict__ emb,
                                const float* __restrict__ te_row,
                                int nodeOff, int n) {
    int i = blockIdx.x * blockDim.x + threadIdx.x;
    if (i < n) g_X[(size_t)nodeOff * HID + i] = emb[i] + te_row[i & (HID - 1)];
}

// tracks: x = track_x @ W^T + b + type_emb[1]; 32 tracks/block, float4 LDS.
#define TLP (FEAT + 4)   // 132: padded row stride (16B aligned, conflict-free f4)
__global__ void track_linear_kernel(const float* __restrict__ tx,
                                    const float* __restrict__ W,
                                    const float* __restrict__ b,
                                    const float* __restrict__ te) {
    __shared__ float shW[HID * TLP];    // [j][k] padded
    __shared__ float shR[32 * FEAT];    // 16KB
    int tid = threadIdx.x;
    for (int i = tid; i < HID * FEAT; i += 256) {
        int j = i >> 7, k = i & (FEAT - 1);
        shW[j * TLP + k] = W[i];
    }
    int base = blockIdx.x * 32;
    const float4* tx4 = reinterpret_cast<const float4*>(tx) + (size_t)base * (FEAT / 4);
    float4* shR4 = reinterpret_cast<float4*>(shR);
    for (int i = tid; i < 32 * FEAT / 4; i += 256) shR4[i] = tx4[i];
    int j = tid & 63, g = tid >> 6;          // g in 0..3, 8 tracks each
    float bias = b[j] + te[HID + j];
    __syncthreads();
    float acc[8];
#pragma unroll
    for (int t = 0; t < 8; t++) acc[t] = bias;
#pragma unroll
    for (int k4 = 0; k4 < FEAT; k4 += 4) {
        float4 w = *reinterpret_cast<const float4*>(&shW[j * TLP + k4]);
#pragma unroll
        for (int t = 0; t < 8; t++) {
            float4 r = *reinterpret_cast<const float4*>(&shR[(g * 8 + t) * FEAT + k4]);
            acc[t] += r.x * w.x + r.y * w.y + r.z * w.z + r.w * w.w;
        }
    }
#pragma unroll
    for (int t = 0; t < 8; t++)
        g_X[(size_t)(OFF_TR + base + g * 8 + t) * HID + j] = acc[t];
}

// Degrees (per-node incidence counts)
__global__ void deg_kernel(const int* __restrict__ A, const int* __restrict__ B,
                           int n, int offA, int offB) {
    int i = blockIdx.x * blockDim.x + threadIdx.x;
    if (i < n) {
        atomicAdd(&g_DEG[A[i] + offA], 1);
        atomicAdd(&g_DEG[B[i] + offB], 1);
    }
}

// Single-block exclusive scan DEG -> ROWPTR
__global__ void scan_kernel() {
    __shared__ int s[1024];
    int tid = threadIdx.x;
    const int CH = (NTOT + 1023) / 1024;   // 157
    int beg = tid * CH;
    int end = beg + CH; if (end > NTOT) end = NTOT; if (beg > NTOT) beg = NTOT;
    int sum = 0;
    for (int i = beg; i < end; i++) sum += g_DEG[i];
    s[tid] = sum;
    __syncthreads();
    for (int off = 1; off < 1024; off <<= 1) {
        int v = (tid >= off) ? s[tid - off] : 0;
        __syncthreads();
        s[tid] += v;
        __syncthreads();
    }
    int run = (tid == 0) ? 0 : s[tid - 1];
    for (int i = beg; i < end; i++) { g_ROWPTR[i] = run; run += g_DEG[i]; }
    if (tid == 1023) g_ROWPTR[NTOT] = run;
}

// Fill adjacency: each undirected pair adds an incidence in both directions.
__global__ void fill_kernel(const int* __restrict__ A, const int* __restrict__ B,
                            int n, int offA, int offB) {
    int i = blockIdx.x * blockDim.x + threadIdx.x;
    if (i < n) {
        int a = A[i] + offA, b = B[i] + offB;
        int pa = atomicAdd(&g_CUR[a], 1);
        g_ADJ[g_ROWPTR[a] + pa] = b;
        int pb = atomicAdd(&g_CUR[b], 1);
        g_ADJ[g_ROWPTR[b] + pb] = a;
    }
}

// Warp per node: mean over neighbor rows -> AGG (written exactly once).
// Lanes 0-15 handle even neighbors (float4 quarter q=lane), 16-31 odd.
__global__ void gather_kernel() {
    int warp = (blockIdx.x * blockDim.x + threadIdx.x) >> 5;
    if (warp >= NTOT) return;
    int lane = threadIdx.x & 31;
    int q = lane & 15, half = lane >> 4;
    int beg = g_ROWPTR[warp], end = g_ROWPTR[warp + 1];
    const float4* X4 = reinterpret_cast<const float4*>(g_X);
    float4 acc = make_float4(0.f, 0.f, 0.f, 0.f);
    for (int e = beg + half; e < end; e += 2) {
        int s = g_ADJ[e];
        float4 v = X4[(size_t)s * 16 + q];
        acc.x += v.x; acc.y += v.y; acc.z += v.z; acc.w += v.w;
    }
    acc.x += __shfl_xor_sync(0xffffffffu, acc.x, 16);
    acc.y += __shfl_xor_sync(0xffffffffu, acc.y, 16);
    acc.z += __shfl_xor_sync(0xffffffffu, acc.z, 16);
    acc.w += __shfl_xor_sync(0xffffffffu, acc.w, 16);
    if (lane < 16) {
        int d = end - beg;
        float inv = (d > 0) ? 1.0f / (float)d : 0.0f;   // deg clamp: sum==0 anyway
        float4 r = make_float4(acc.x * inv, acc.y * inv, acc.z * inv, acc.w * inv);
        reinterpret_cast<float4*>(g_AGG)[(size_t)warp * 16 + q] = r;
    }
}

// x_new = relu(AGG @ Wl^T + bl + x @ Wr^T). 16 nodes/block, float4 LDS.
#define UWP (HID + 4)    // 68: padded stride
__global__ void update_kernel(const float* __restrict__ Wl,
                              const float* __restrict__ bl,
                              const float* __restrict__ Wr,
                              float* __restrict__ OUT) {
    __shared__ float shWl[HID * UWP];
    __shared__ float shWr[HID * UWP];
    __shared__ float shA[16 * HID];
    __shared__ float shX[16 * HID];
    int tid = threadIdx.x;
    for (int i = tid; i < HID * HID; i += 256) {
        int j = i >> 6, k = i & 63;
        shWl[j * UWP + k] = Wl[i];
        shWr[j * UWP + k] = Wr[i];
    }
    int base = blockIdx.x * 16;
    {
        const float4* A4 = reinterpret_cast<const float4*>(g_AGG) + (size_t)base * 16;
        const float4* Xx4 = reinterpret_cast<const float4*>(g_X) + (size_t)base * 16;
        float4* sA4 = reinterpret_cast<float4*>(shA);
        float4* sX4 = reinterpret_cast<float4*>(shX);
        for (int i = tid; i < 16 * HID / 4; i += 256) { sA4[i] = A4[i]; sX4[i] = Xx4[i]; }
    }
    int j = tid & 63, g = tid >> 6;
    float bias = bl[j];
    __syncthreads();
    float acc[4] = {bias, bias, bias, bias};
#pragma unroll
    for (int k4 = 0; k4 < HID; k4 += 4) {
        float4 wl = *reinterpret_cast<const float4*>(&shWl[j * UWP + k4]);
        float4 wr = *reinterpret_cast<const float4*>(&shWr[j * UWP + k4]);
#pragma unroll
        for (int t = 0; t < 4; t++) {
            int nn = g * 4 + t;
            float4 a = *reinterpret_cast<const float4*>(&shA[nn * HID + k4]);
            float4 x = *reinterpret_cast<const float4*>(&shX[nn * HID + k4]);
            acc[t] += a.x * wl.x + a.y * wl.y + a.z * wl.z + a.w * wl.w
                    + x.x * wr.x + x.y * wr.y + x.z * wr.z + x.w * wr.w;
        }
    }
    float* o = OUT ? OUT : g_X;
#pragma unroll
    for (int t = 0; t < 4; t++)
        o[(size_t)(base + g * 4 + t) * HID + j] = fmaxf(acc[t], 0.f);
}

// ---------------------------------------------------------------------------
extern "C" void kernel_launch(void* const* d_in, const int* in_sizes, int n_in,
                              void* d_out, int out_size) {
    const float* track_x      = (const float*)d_in[0];
    const int*   pl_tr_src    = (const int*)d_in[1];
    const int*   pl_tr_dst    = (const int*)d_in[2];
    const int*   tr_ar_src    = (const int*)d_in[3];
    const int*   tr_ar_dst    = (const int*)d_in[4];
    const float* playlist_emb = (const float*)d_in[5];
    const float* artist_emb   = (const float*)d_in[6];
    const float* track_W      = (const float*)d_in[7];
    const float* track_b      = (const float*)d_in[8];
    const float* type_emb     = (const float*)d_in[9];
    const float* conv_Wl      = (const float*)d_in[10];
    const float* conv_bl      = (const float*)d_in[11];
    const float* conv_Wr      = (const float*)d_in[12];
    float* out = (float*)d_out;

    int nE1 = in_sizes[1];   // pl<->tr pairs
    int nE2 = in_sizes[3];   // tr<->ar pairs

    // init + CSR build
    zero_kernel<<<320, 256>>>();
    init_emb_kernel<<<(NUM_PL * HID + 255) / 256, 256>>>(playlist_emb, type_emb, 0, NUM_PL * HID);
    init_emb_kernel<<<(NUM_AR * HID + 255) / 256, 256>>>(artist_emb, type_emb + 2 * HID, OFF_AR, NUM_AR * HID);
    track_linear_kernel<<<NUM_TR / 32, 256>>>(track_x, track_W, track_b, type_emb);
    deg_kernel<<<(nE1 + 255) / 256, 256>>>(pl_tr_src, pl_tr_dst, nE1, 0, OFF_TR);
    deg_kernel<<<(nE2 + 255) / 256, 256>>>(tr_ar_src, tr_ar_dst, nE2, OFF_TR, OFF_AR);
    scan_kernel<<<1, 1024>>>();
    fill_kernel<<<(nE1 + 255) / 256, 256>>>(pl_tr_src, pl_tr_dst, nE1, 0, OFF_TR);
    fill_kernel<<<(nE2 + 255) / 256, 256>>>(tr_ar_src, tr_ar_dst, nE2, OFF_TR, OFF_AR);

    // layer 0
    gather_kernel<<<(NTOT + 7) / 8, 256>>>();
    update_kernel<<<NTOT / 16, 256>>>(conv_Wl, conv_bl, conv_Wr, nullptr);

    // layer 1
    gather_kernel<<<(NTOT + 7) / 8, 256>>>();
    update_kernel<<<NTOT / 16, 256>>>(conv_Wl + HID * HID, conv_bl + HID, conv_Wr + HID * HID, out);
}

// round 4
// speedup vs baseline: 1.9908x; 1.0142x over previous
#include <cuda_runtime.h>

#define NUM_PL 50000
#define NUM_TR 100000
#define NUM_AR 10000
#define NTOT   160000
#define HID    64
#define FEAT   128
#define OFF_TR NUM_PL
#define OFF_AR (NUM_PL + NUM_TR)
#define NEDGE  4200000   // total directed incidences

// Scratch (device globals — no allocation allowed)
__device__ float g_X[(size_t)NTOT * HID];    // layer input 0
__device__ float g_X2[(size_t)NTOT * HID];   // layer-0 output / layer-1 input
__device__ int   g_DEG[NTOT];
__device__ int   g_CUR[NTOT];
__device__ int   g_ROWPTR[NTOT + 1];
__device__ int   g_ADJ[NEDGE];

// ---------------------------------------------------------------------------
__global__ void zero_kernel() {
    int i = blockIdx.x * blockDim.x + threadIdx.x;
    int stride = gridDim.x * blockDim.x;
    for (int k = i; k < NTOT; k += stride) { g_DEG[k] = 0; g_CUR[k] = 0; }
}

__global__ void init_emb_kernel(const float* __restrict__ emb,
                                const float* __restrict__ te_row,
                                int nodeOff, int n) {
    int i = blockIdx.x * blockDim.x + threadIdx.x;
    if (i < n) g_X[(size_t)nodeOff * HID + i] = emb[i] + te_row[i & (HID - 1)];
}

// tracks: x = track_x @ W^T + b + type_emb[1]; 32 tracks/block.
// Each thread computes 2 outputs (j, j+32) for 4 tracks -> 6 LDS.128 / 32 FMA.
#define TLP (FEAT + 4)
__global__ void track_linear_kernel(const float* __restrict__ tx,
                                    const float* __restrict__ W,
                                    const float* __restrict__ b,
                                    const float* __restrict__ te) {
    __shared__ float shW[HID * TLP];
    __shared__ float shR[32 * FEAT];
    int tid = threadIdx.x;
    for (int i = tid; i < HID * FEAT; i += 256) {
        int j = i >> 7, k = i & (FEAT - 1);
        shW[j * TLP + k] = W[i];
    }
    int base = blockIdx.x * 32;
    const float4* tx4 = reinterpret_cast<const float4*>(tx) + (size_t)base * (FEAT / 4);
    float4* shR4 = reinterpret_cast<float4*>(shR);
    for (int i = tid; i < 32 * FEAT / 4; i += 256) shR4[i] = tx4[i];
    int j0 = tid & 31, g = tid >> 5;          // g in 0..7, 4 tracks each
    float bias0 = b[j0] + te[HID + j0];
    float bias1 = b[j0 + 32] + te[HID + j0 + 32];
    __syncthreads();
    float acc0[4] = {bias0, bias0, bias0, bias0};
    float acc1[4] = {bias1, bias1, bias1, bias1};
#pragma unroll
    for (int k4 = 0; k4 < FEAT; k4 += 4) {
        float4 w0 = *reinterpret_cast<const float4*>(&shW[j0 * TLP + k4]);
        float4 w1 = *reinterpret_cast<const float4*>(&shW[(j0 + 32) * TLP + k4]);
#pragma unroll
        for (int t = 0; t < 4; t++) {
            float4 r = *reinterpret_cast<const float4*>(&shR[(g * 4 + t) * FEAT + k4]);
            acc0[t] += r.x * w0.x + r.y * w0.y + r.z * w0.z + r.w * w0.w;
            acc1[t] += r.x * w1.x + r.y * w1.y + r.z * w1.z + r.w * w1.w;
        }
    }
#pragma unroll
    for (int t = 0; t < 4; t++) {
        size_t row = (size_t)(OFF_TR + base + g * 4 + t) * HID;
        g_X[row + j0]      = acc0[t];
        g_X[row + j0 + 32] = acc1[t];
    }
}

__global__ void deg_kernel(const int* __restrict__ A, const int* __restrict__ B,
                           int n, int offA, int offB) {
    int i = blockIdx.x * blockDim.x + threadIdx.x;
    if (i < n) {
        atomicAdd(&g_DEG[A[i] + offA], 1);
        atomicAdd(&g_DEG[B[i] + offB], 1);
    }
}

// Single-block exclusive scan DEG -> ROWPTR
__global__ void scan_kernel() {
    __shared__ int s[1024];
    int tid = threadIdx.x;
    const int CH = (NTOT + 1023) / 1024;
    int beg = tid * CH;
    int end = beg + CH; if (end > NTOT) end = NTOT; if (beg > NTOT) beg = NTOT;
    int sum = 0;
    for (int i = beg; i < end; i++) sum += g_DEG[i];
    s[tid] = sum;
    __syncthreads();
    for (int off = 1; off < 1024; off <<= 1) {
        int v = (tid >= off) ? s[tid - off] : 0;
        __syncthreads();
        s[tid] += v;
        __syncthreads();
    }
    int run = (tid == 0) ? 0 : s[tid - 1];
    for (int i = beg; i < end; i++) { g_ROWPTR[i] = run; run += g_DEG[i]; }
    if (tid == 1023) g_ROWPTR[NTOT] = run;
}

__global__ void fill_kernel(const int* __restrict__ A, const int* __restrict__ B,
                            int n, int offA, int offB) {
    int i = blockIdx.x * blockDim.x + threadIdx.x;
    if (i < n) {
        int a = A[i] + offA, b = B[i] + offB;
        int pa = atomicAdd(&g_CUR[a], 1);
        g_ADJ[g_ROWPTR[a] + pa] = b;
        int pb = atomicAdd(&g_CUR[b], 1);
        g_ADJ[g_ROWPTR[b] + pb] = a;
    }
}

// Fused SAGE layer: 16 nodes/block.
//   Phase 1: 8 warps, each gathers neighbor means for 2 nodes into shA
//            (unroll x2 per half-warp -> 4 loads in flight / warp).
//   Phase 2: shared-mem GEMM  out = relu(shA@Wl^T + bl + shX@Wr^T).
#define UWP (HID + 4)
__global__ void fused_layer_kernel(const float* __restrict__ Xin,
                                   float* __restrict__ Xout,
                                   const float* __restrict__ Wl,
                                   const float* __restrict__ bl,
                                   const float* __restrict__ Wr) {
    __shared__ float shWl[HID * UWP];
    __shared__ float shWr[HID * UWP];
    __shared__ float shA[16 * HID];
    __shared__ float shX[16 * HID];
    int tid = threadIdx.x;
    int base = blockIdx.x * 16;
    for (int i = tid; i < HID * HID; i += 256) {
        int j = i >> 6, k = i & 63;
        shWl[j * UWP + k] = Wl[i];
        shWr[j * UWP + k] = Wr[i];
    }
    const float4* Xin4 = reinterpret_cast<const float4*>(Xin);
    {   // self rows, coalesced
        float4* sX4 = reinterpret_cast<float4*>(shX);
        sX4[tid] = Xin4[(size_t)base * 16 + tid];   // 256 float4 = 16 rows
    }
    // gather
    {
        int warp = tid >> 5, lane = tid & 31;
        int q = lane & 15, half = lane >> 4;
#pragma unroll
        for (int i2 = 0; i2 < 2; i2++) {
            int nl = warp * 2 + i2;
            int node = base + nl;
            int beg = g_ROWPTR[node], end = g_ROWPTR[node + 1];
            float4 acc = make_float4(0.f, 0.f, 0.f, 0.f);
            int e = beg + half;
            for (; e + 2 < end; e += 4) {
                int s0 = g_ADJ[e], s1 = g_ADJ[e + 2];
                float4 v0 = Xin4[(size_t)s0 * 16 + q];
                float4 v1 = Xin4[(size_t)s1 * 16 + q];
                acc.x += v0.x + v1.x; acc.y += v0.y + v1.y;
                acc.z += v0.z + v1.z; acc.w += v0.w + v1.w;
            }
            if (e < end) {
                float4 v = Xin4[(size_t)g_ADJ[e] * 16 + q];
                acc.x += v.x; acc.y += v.y; acc.z += v.z; acc.w += v.w;
            }
            acc.x += __shfl_xor_sync(0xffffffffu, acc.x, 16);
            acc.y += __shfl_xor_sync(0xffffffffu, acc.y, 16);
            acc.z += __shfl_xor_sync(0xffffffffu, acc.z, 16);
            acc.w += __shfl_xor_sync(0xffffffffu, acc.w, 16);
            if (lane < 16) {
                int d = end - beg;
                float inv = (d > 0) ? 1.0f / (float)d : 0.0f;
                reinterpret_cast<float4*>(shA)[nl * 16 + q] =
                    make_float4(acc.x * inv, acc.y * inv, acc.z * inv, acc.w * inv);
            }
        }
    }
    __syncthreads();
    // GEMM
    int j = tid & 63, g = tid >> 6;
    float bias = bl[j];
    float acc[4] = {bias, bias, bias, bias};
#pragma unroll
    for (int k4 = 0; k4 < HID; k4 += 4) {
        float4 wl = *reinterpret_cast<const float4*>(&shWl[j * UWP + k4]);
        float4 wr = *reinterpret_cast<const float4*>(&shWr[j * UWP + k4]);
#pragma unroll
        for (int t = 0; t < 4; t++) {
            int nn = g * 4 + t;
            float4 a = *reinterpret_cast<const float4*>(&shA[nn * HID + k4]);
            float4 x = *reinterpret_cast<const float4*>(&shX[nn * HID + k4]);
            acc[t] += a.x * wl.x + a.y * wl.y + a.z * wl.z + a.w * wl.w
                    + x.x * wr.x + x.y * wr.y + x.z * wr.z + x.w * wr.w;
        }
    }
#pragma unroll
    for (int t = 0; t < 4; t++)
        Xout[(size_t)(base + g * 4 + t) * HID + j] = fmaxf(acc[t], 0.f);
}

// ---------------------------------------------------------------------------
extern "C" void kernel_launch(void* const* d_in, const int* in_sizes, int n_in,
                              void* d_out, int out_size) {
    const float* track_x      = (const float*)d_in[0];
    const int*   pl_tr_src    = (const int*)d_in[1];
    const int*   pl_tr_dst    = (const int*)d_in[2];
    const int*   tr_ar_src    = (const int*)d_in[3];
    const int*   tr_ar_dst    = (const int*)d_in[4];
    const float* playlist_emb = (const float*)d_in[5];
    const float* artist_emb   = (const float*)d_in[6];
    const float* track_W      = (const float*)d_in[7];
    const float* track_b      = (const float*)d_in[8];
    const float* type_emb     = (const float*)d_in[9];
    const float* conv_Wl      = (const float*)d_in[10];
    const float* conv_bl      = (const float*)d_in[11];
    const float* conv_Wr      = (const float*)d_in[12];
    float* out = (float*)d_out;

    int nE1 = in_sizes[1];
    int nE2 = in_sizes[3];

    // init + CSR build
    zero_kernel<<<320, 256>>>();
    init_emb_kernel<<<(NUM_PL * HID + 255) / 256, 256>>>(playlist_emb, type_emb, 0, NUM_PL * HID);
    init_emb_kernel<<<(NUM_AR * HID + 255) / 256, 256>>>(artist_emb, type_emb + 2 * HID, OFF_AR, NUM_AR * HID);
    track_linear_kernel<<<NUM_TR / 32, 256>>>(track_x, track_W, track_b, type_emb);
    deg_kernel<<<(nE1 + 255) / 256, 256>>>(pl_tr_src, pl_tr_dst, nE1, 0, OFF_TR);
    deg_kernel<<<(nE2 + 255) / 256, 256>>>(tr_ar_src, tr_ar_dst, nE2, OFF_TR, OFF_AR);
    scan_kernel<<<1, 1024>>>();
    fill_kernel<<<(nE1 + 255) / 256, 256>>>(pl_tr_src, pl_tr_dst, nE1, 0, OFF_TR);
    fill_kernel<<<(nE2 + 255) / 256, 256>>>(tr_ar_src, tr_ar_dst, nE2, OFF_TR, OFF_AR);

    // two fused SAGE layers
    float* X2;  cudaGetSymbolAddress((void**)&X2, g_X2);
    float* X1;  cudaGetSymbolAddress((void**)&X1, g_X);
    fused_layer_kernel<<<NTOT / 16, 256>>>(X1, X2, conv_Wl, conv_bl, conv_Wr);
    fused_layer_kernel<<<NTOT / 16, 256>>>(X2, out, conv_Wl + HID * HID, conv_bl + HID,
                                           conv_Wr + HID * HID);
}